// round 17
// baseline (speedup 1.0000x reference)
#include <cuda_runtime.h>
#include <cuda_fp16.h>
#include <stdint.h>
#include <math.h>

#define NE 50000
#define HD 256
#define KD 768
#define KB1 288   // phase-2 K: 256 he + 32 q (11 real + pad)

// SMEM layout (halves)
#define A2_STRIDE 296                            // 592 B row stride: conflict-free ldsm
#define A2_HALVES (128 * A2_STRIDE)              // 37888
#define S0 A2_HALVES                             // phase-1 staging base (halves)
#define P1_STAGE 15360                           // Ah(5120) + Bh(10240)
#define S0P2 (S0 + 2 * P1_STAGE)                 // 68608: phase-2 staging base
#define P2_STAGE 10240                           // Bh only
#define KAN_OFF (S0P2 + 2 * P2_STAGE)            // 89088 halves = 178176 B
#define KAN_FLOATS 4608                          // sbw 512 + ssw 4096
#define SMEM_BYTES (KAN_OFF * 2 + KAN_FLOATS * 4)  // 196608

// ---------------- scratch ----------------------------------------------------
__device__ __half g_WeH[HD * KD];          // W_e fp16 [n][k] k<768
__device__ __half g_WcH[HD * KB1];         // W' fp16 [n][k] k<288
__device__ float g_bias2[HD];              // bl_ue + bl_se
__device__ float g_sum8[NE * 8];
__device__ float g_sum1[NE];
__device__ int   g_cnt_ue[NE];
__device__ int   g_cnt_se[NE];

// ---------------- zero accumulators (every graph replay) --------------------
__global__ void zero_kernel() {
    int i = blockIdx.x * blockDim.x + threadIdx.x;
    int stride = gridDim.x * blockDim.x;
    for (int j = i; j < NE * 8; j += stride) g_sum8[j] = 0.f;
    for (int j = i; j < NE; j += stride) { g_sum1[j] = 0.f; g_cnt_ue[j] = 0; g_cnt_se[j] = 0; }
}

// ---------------- merged prep + prep2 + agg (disjoint writes) ---------------
__global__ void prep_all(const float* __restrict__ W_e,
                         const float* __restrict__ Wr_ue, const float* __restrict__ Wr_se,
                         const float* __restrict__ bl_ue, const float* __restrict__ bl_se,
                         const float* __restrict__ Wl_ue, const float* __restrict__ W_u,
                         const float* __restrict__ b_u,
                         const float* __restrict__ Wl_se, const float* __restrict__ W_s,
                         const float* __restrict__ b_s,
                         const int* __restrict__ ue_src, const int* __restrict__ ue_dst,
                         const float* __restrict__ x_url, int n_ue,
                         const int* __restrict__ se_src, const int* __restrict__ se_dst,
                         const float* __restrict__ x_sender, int n_se) {
    int b = blockIdx.x;
    int tid = threadIdx.x;
    if (b < 768) {
        // ---- prep: W_e convert, combined Wr, bias2 ----
        int idx = b * 256 + tid;
        if (idx < HD) g_bias2[idx] = bl_ue[idx] + bl_se[idx];
        g_WeH[idx] = __float2half_rn(W_e[idx]);
        if (idx < HD * HD) {
            int n = idx >> 8, k = idx & 255;
            g_WcH[n * KB1 + k] = __float2half_rn(Wr_ue[idx] + Wr_se[idx]);
        }
    } else if (b < 800) {
        // ---- prep2: rank-11 correction columns (8 n per block) ----
        int n = (b - 768) * 8 + (tid >> 5);
        int c = tid & 31;
        float acc = 0.f;
        if (c < 8) {
            for (int h = 0; h < HD; h++) acc += Wl_ue[n * HD + h] * W_u[h * 8 + c];
        } else if (c == 8) {
            for (int h = 0; h < HD; h++) acc += Wl_ue[n * HD + h] * b_u[h];
        } else if (c == 9) {
            for (int h = 0; h < HD; h++) acc += Wl_se[n * HD + h] * W_s[h];
        } else if (c == 10) {
            for (int h = 0; h < HD; h++) acc += Wl_se[n * HD + h] * b_s[h];
        }
        g_WcH[n * KB1 + 256 + c] = __float2half_rn(acc);
    } else {
        // ---- agg: edge aggregation (zeroed by zero_kernel beforehand) ----
        int e = (b - 800) * 256 + tid;
        if (e < n_ue) {
            int s = ue_src[e], d = ue_dst[e];
            const float4* xu = (const float4*)(x_url + (size_t)s * 8);
            float4 a = xu[0], bb = xu[1];
            float* p = g_sum8 + (size_t)d * 8;
            asm volatile("red.global.add.v4.f32 [%0], {%1,%2,%3,%4};"
                         :: "l"(p), "f"(a.x), "f"(a.y), "f"(a.z), "f"(a.w) : "memory");
            asm volatile("red.global.add.v4.f32 [%0], {%1,%2,%3,%4};"
                         :: "l"(p + 4), "f"(bb.x), "f"(bb.y), "f"(bb.z), "f"(bb.w) : "memory");
            asm volatile("red.global.add.s32 [%0], %1;" :: "l"(g_cnt_ue + d), "r"(1) : "memory");
        } else {
            int e2 = e - n_ue;
            if (e2 < n_se) {
                int d = se_dst[e2];
                float v = x_sender[se_src[e2]];
                asm volatile("red.global.add.f32 [%0], %1;" :: "l"(g_sum1 + d), "f"(v) : "memory");
                asm volatile("red.global.add.s32 [%0], %1;" :: "l"(g_cnt_se + d), "r"(1) : "memory");
            }
        }
    }
}

// ---------------- helpers -----------------------------------------------------
__device__ __forceinline__ void cp16(uint32_t d, const void* s) {
    asm volatile("cp.async.cg.shared.global [%0], [%1], 16;" :: "r"(d), "l"(s));
}
#define CP_COMMIT() asm volatile("cp.async.commit_group;")
#define CP_WAIT0()  asm volatile("cp.async.wait_group 0;")

__device__ __forceinline__ void ldsm4(uint32_t addr, uint32_t& r0, uint32_t& r1,
                                      uint32_t& r2, uint32_t& r3) {
    asm volatile("ldmatrix.sync.aligned.m8n8.x4.shared.b16 {%0,%1,%2,%3}, [%4];"
                 : "=r"(r0), "=r"(r1), "=r"(r2), "=r"(r3) : "r"(addr));
}

__device__ __forceinline__ void mma16816(float* c, const uint32_t* a, uint32_t b0, uint32_t b1) {
    asm volatile("mma.sync.aligned.m16n8k16.row.col.f32.f16.f16.f32 "
                 "{%0,%1,%2,%3}, {%4,%5,%6,%7}, {%8,%9}, {%0,%1,%2,%3};"
                 : "+f"(c[0]), "+f"(c[1]), "+f"(c[2]), "+f"(c[3])
                 : "r"(a[0]), "r"(a[1]), "r"(a[2]), "r"(a[3]), "r"(b0), "r"(b1));
}

// ---------------- fully fused: proj + conv + activation + KAN ---------------
// 1024 threads, 32 warps (4m x 8n), warp tile 32x32, block tile 128x256.
__global__ __launch_bounds__(1024, 1) void fused_gemm(const float* __restrict__ x_email,
                                                      const float* __restrict__ b_e,
                                                      const float* __restrict__ gate,
                                                      const float* __restrict__ base_w,
                                                      const float* __restrict__ spline_w,
                                                      float* __restrict__ out) {
    extern __shared__ __half dsm[];
    const uint32_t sbase = (uint32_t)__cvta_generic_to_shared(dsm);
    __half* A2 = dsm;
    float* kanw = (float*)(dsm + KAN_OFF);
    float* pacc = (float*)(dsm + S0);   // aliases dead phase-1 staging: [wn][128][2]

    const int tid = threadIdx.x;
    const int lane = tid & 31;
    const int warp = tid >> 5;      // 0..31
    const int wm = warp & 3;        // 4 m-slabs of 32
    const int wn = warp >> 2;       // 8 n-slabs of 32
    const int m0 = blockIdx.x * 128;

    const int a_row_off = ((lane >> 3) & 1) * 8 + (lane & 7);
    const int a_k_off   = ((lane >> 4) & 1) * 8;
    const int b_row_off = ((lane >> 4) & 1) * 8 + (lane & 7);
    const int b_k_off   = ((lane >> 3) & 1) * 8;
    const int g = lane >> 2, t = lane & 3;

    // ---- KAN weight load ----
    for (int i = tid; i < 512; i += 1024) kanw[i] = base_w[i];
    for (int i = tid; i < 4096; i += 1024) {
        int o = i >> 11;
        int h = (i >> 3) & 255;
        int gg = i & 7;
        kanw[512 + gg * 512 + o * 256 + h] = spline_w[i];
    }

    float C[2][4][4];
#pragma unroll
    for (int i = 0; i < 2; i++)
#pragma unroll
        for (int j = 0; j < 4; j++)
#pragma unroll
            for (int q = 0; q < 4; q++) C[i][j][q] = 0.f;

    float4 Ar;

    auto issueB2 = [&](int kt, int buf) {
        const int k0 = kt * 32;
        uint32_t bh = sbase + (uint32_t)(S0P2 + buf * P2_STAGE) * 2u;
        int row = tid >> 2, m = tid & 3;
        cp16(bh + (uint32_t)(row * 40 + m * 8) * 2,
             g_WcH + (size_t)row * KB1 + k0 + m * 8);
        CP_COMMIT();
    };

    // ================= PHASE 1: K = 768, chunks of 32 =================
    auto issueB1 = [&](int kt, int buf) {
        const int k0 = kt * 32;
        uint32_t bh = sbase + (uint32_t)(S0 + buf * P1_STAGE + 5120) * 2u;
        int row = tid >> 2, m = tid & 3;   // 256 rows x 4 chunks
        cp16(bh + (uint32_t)(row * 40 + m * 8) * 2,
             g_WeH + (size_t)row * KD + k0 + m * 8);
        CP_COMMIT();
    };
    auto loadA1 = [&](int kt) {
        const int k0 = kt * 32;
        int row = tid >> 3, c4 = (tid & 7) << 2;  // 128 rows x 8 float4
        int gr = m0 + row;
        Ar = (gr < NE) ? *(const float4*)(x_email + (size_t)gr * KD + k0 + c4)
                       : make_float4(0.f, 0.f, 0.f, 0.f);
    };
    auto storeA1 = [&](int buf) {
        __half* Ah = dsm + S0 + buf * P1_STAGE;
        int row = tid >> 3, c4 = (tid & 7) << 2;
        __half2 hp0; hp0.x = __float2half_rn(Ar.x); hp0.y = __float2half_rn(Ar.y);
        __half2 hp1; hp1.x = __float2half_rn(Ar.z); hp1.y = __float2half_rn(Ar.w);
        *(__half2*)(Ah + row * 40 + c4)     = hp0;
        *(__half2*)(Ah + row * 40 + c4 + 2) = hp1;
    };

    loadA1(0);
    issueB1(0, 0);

    for (int kt = 0; kt < 24; kt++) {
        const int cur = kt & 1;
        storeA1(cur);
        CP_WAIT0();
        __syncthreads();
        if (kt + 1 < 24) {
            issueB1(kt + 1, cur ^ 1);
            loadA1(kt + 1);
        } else {
            issueB2(0, 0);   // cross-phase prefetch: phase-2 B stage 0
        }
        const uint32_t sAh = sbase + (uint32_t)(S0 + cur * P1_STAGE) * 2u;
        const uint32_t sBh = sbase + (uint32_t)(S0 + cur * P1_STAGE + 5120) * 2u;
#pragma unroll
        for (int kh = 0; kh < 2; kh++) {
            uint32_t Af[2][4];
#pragma unroll
            for (int mf = 0; mf < 2; mf++) {
                int row = wm * 32 + mf * 16 + a_row_off;
                uint32_t off = (uint32_t)(row * 40 + kh * 16 + a_k_off) * 2;
                ldsm4(sAh + off, Af[mf][0], Af[mf][1], Af[mf][2], Af[mf][3]);
            }
            uint32_t Bf[2][4];
#pragma unroll
            for (int nf = 0; nf < 2; nf++) {
                int row = wn * 32 + nf * 16 + b_row_off;
                uint32_t off = (uint32_t)(row * 40 + kh * 16 + b_k_off) * 2;
                ldsm4(sBh + off, Bf[nf][0], Bf[nf][1], Bf[nf][2], Bf[nf][3]);
            }
#pragma unroll
            for (int mf = 0; mf < 2; mf++) {
#pragma unroll
                for (int j = 0; j < 4; j++) {
                    int nf = j >> 1;
                    int hh = j & 1;
                    mma16816(C[mf][j], Af[mf], Bf[nf][hh * 2], Bf[nf][hh * 2 + 1]);
                }
            }
        }
    }

    // ---- epilogue 1: he_pre + b_e -> fp16 A2 cols 0..255
#pragma unroll
    for (int mf = 0; mf < 2; mf++) {
        int rl0 = wm * 32 + mf * 16 + g;
#pragma unroll
        for (int j = 0; j < 4; j++) {
            int col = wn * 32 + j * 8 + t * 2;
            float b0 = b_e[col], b1 = b_e[col + 1];
#pragma unroll
            for (int half = 0; half < 2; half++) {
                int rl = rl0 + half * 8;
                __half2 hp;
                hp.x = __float2half_rn(C[mf][j][half * 2 + 0] + b0);
                hp.y = __float2half_rn(C[mf][j][half * 2 + 1] + b1);
                *(__half2*)&A2[rl * A2_STRIDE + col] = hp;
            }
        }
    }

    // ---- q vector: A2 cols 256..287 (8 threads per row, 4 cols each)
    {
        int rl = tid >> 3;
        int cc = (tid & 7) * 4;
        int gr = m0 + rl;
        float qv[4];
#pragma unroll
        for (int i = 0; i < 4; i++) qv[i] = 0.f;
        if (gr < NE && cc < 12) {
            int cu = g_cnt_ue[gr];
            int cs = g_cnt_se[gr];
            float invu = (cu > 0) ? 1.f / (float)cu : 0.f;
#pragma unroll
            for (int i = 0; i < 4; i++) {
                int qi = cc + i;
                float v = 0.f;
                if (qi < 8)       v = g_sum8[(size_t)gr * 8 + qi] * invu;
                else if (qi == 8)  v = (cu > 0) ? 1.f : 0.f;
                else if (qi == 9)  v = (cs > 0) ? g_sum1[gr] / (float)cs : 0.f;
                else if (qi == 10) v = (cs > 0) ? 1.f : 0.f;
                qv[i] = v;
            }
        }
        __half2 hp0; hp0.x = __float2half_rn(qv[0]); hp0.y = __float2half_rn(qv[1]);
        __half2 hp1; hp1.x = __float2half_rn(qv[2]); hp1.y = __float2half_rn(qv[3]);
        *(__half2*)&A2[rl * A2_STRIDE + 256 + cc]     = hp0;
        *(__half2*)&A2[rl * A2_STRIDE + 256 + cc + 2] = hp1;
    }
    __syncthreads();

    // ================= PHASE 2: K = 288, fp16-hi weights =================
#pragma unroll
    for (int i = 0; i < 2; i++)
#pragma unroll
        for (int j = 0; j < 4; j++)
#pragma unroll
            for (int q = 0; q < 4; q++) C[i][j][q] = 0.f;

    for (int kt = 0; kt < 9; kt++) {
        const int cur = kt & 1;
        CP_WAIT0();
        __syncthreads();
        if (kt + 1 < 9) issueB2(kt + 1, cur ^ 1);

        const uint32_t sBh = sbase + (uint32_t)(S0P2 + cur * P2_STAGE) * 2u;
#pragma unroll
        for (int kh = 0; kh < 2; kh++) {
            uint32_t Af[2][4];
#pragma unroll
            for (int mf = 0; mf < 2; mf++) {
                int row = wm * 32 + mf * 16 + a_row_off;
                uint32_t off = (uint32_t)(row * A2_STRIDE + kt * 32 + kh * 16 + a_k_off) * 2;
                ldsm4(sbase + off, Af[mf][0], Af[mf][1], Af[mf][2], Af[mf][3]);
            }
            uint32_t Bf[2][4];
#pragma unroll
            for (int nf = 0; nf < 2; nf++) {
                int row = wn * 32 + nf * 16 + b_row_off;
                uint32_t off = (uint32_t)(row * 40 + kh * 16 + b_k_off) * 2;
                ldsm4(sBh + off, Bf[nf][0], Bf[nf][1], Bf[nf][2], Bf[nf][3]);
            }
#pragma unroll
            for (int mf = 0; mf < 2; mf++) {
#pragma unroll
                for (int j = 0; j < 4; j++) {
                    int nf = j >> 1;
                    int hh = j & 1;
                    mma16816(C[mf][j], Af[mf], Bf[nf][hh * 2], Bf[nf][hh * 2 + 1]);
                }
            }
        }
    }

    // ---- epilogue 2 + register-direct KAN (no he SMEM roundtrip) ----
    const float alpha = 1.f / (1.f + expf(-gate[0]));
    const float c6 = 1.f / 6.f;
    const float* sbw = kanw;
    const float* ssw = kanw + 512;
    float acc[2][2][2];   // [mf][half][o]
#pragma unroll
    for (int i = 0; i < 2; i++)
#pragma unroll
        for (int j = 0; j < 2; j++) { acc[i][j][0] = 0.f; acc[i][j][1] = 0.f; }

#pragma unroll
    for (int mf = 0; mf < 2; mf++) {
#pragma unroll
        for (int j = 0; j < 4; j++) {
            int col = wn * 32 + j * 8 + t * 2;
            float b0 = g_bias2[col], b1 = g_bias2[col + 1];
#pragma unroll
            for (int half = 0; half < 2; half++) {
                int rl = wm * 32 + mf * 16 + half * 8 + g;
                __half2 rh = *(const __half2*)&A2[rl * A2_STRIDE + col];
#pragma unroll
                for (int e = 0; e < 2; e++) {
                    float v = C[mf][j][half * 2 + e] + (e ? b1 : b0);
                    float u = 0.5f * v; u = u > 0.f ? u : 0.2f * u;
                    float rr = e ? __high2float(rh) : __low2float(rh);
                    float x = alpha * u + (1.f - alpha) * rr;
                    int cc = col + e;
                    float sil = x * __fdividef(1.f, 1.f + __expf(-x));
                    acc[mf][half][0] += sil * sbw[cc];
                    acc[mf][half][1] += sil * sbw[256 + cc];
                    float tt = (x + 2.2f) * 2.5f;
                    float fj = floorf(tt);
                    int ji = (int)fj;
                    if (ji >= 0 && ji < 11) {
                        float uu = tt - fj;
                        float u2 = uu * uu, u3 = u2 * uu;
                        float p0 = u3 * c6;
                        float p1 = (1.f + 3.f * (uu + u2) - 3.f * u3) * c6;
                        float p2 = (4.f - 6.f * u2 + 3.f * u3) * c6;
                        float om = 1.f - uu;
                        float p3 = om * om * om * c6;
                        if (ji < 8) {
                            acc[mf][half][0] += p0 * ssw[ji * 512 + cc];
                            acc[mf][half][1] += p0 * ssw[ji * 512 + 256 + cc];
                        }
                        int g1 = ji - 1;
                        if (g1 >= 0 && g1 < 8) {
                            acc[mf][half][0] += p1 * ssw[g1 * 512 + cc];
                            acc[mf][half][1] += p1 * ssw[g1 * 512 + 256 + cc];
                        }
                        int g2 = ji - 2;
                        if (g2 >= 0 && g2 < 8) {
                            acc[mf][half][0] += p2 * ssw[g2 * 512 + cc];
                            acc[mf][half][1] += p2 * ssw[g2 * 512 + 256 + cc];
                        }
                        int g3 = ji - 3;
                        if (g3 >= 0) {
                            acc[mf][half][0] += p3 * ssw[g3 * 512 + cc];
                            acc[mf][half][1] += p3 * ssw[g3 * 512 + 256 + cc];
                        }
                    }
                }
            }
        }
    }

    // reduce across the 4 t-lanes (same g), then store per-warp partials
#pragma unroll
    for (int mf = 0; mf < 2; mf++)
#pragma unroll
        for (int half = 0; half < 2; half++)
#pragma unroll
            for (int o = 0; o < 2; o++) {
                float a = acc[mf][half][o];
                a += __shfl_xor_sync(0xffffffff, a, 1);
                a += __shfl_xor_sync(0xffffffff, a, 2);
                acc[mf][half][o] = a;
            }
    if (t == 0) {
#pragma unroll
        for (int mf = 0; mf < 2; mf++)
#pragma unroll
            for (int half = 0; half < 2; half++) {
                int rl = wm * 32 + mf * 16 + half * 8 + g;
                pacc[(wn * 128 + rl) * 2 + 0] = acc[mf][half][0];
                pacc[(wn * 128 + rl) * 2 + 1] = acc[mf][half][1];
            }
    }
    __syncthreads();

    // final 8-way reduction: 256 threads, one (row, output) each
    if (tid < 256) {
        int rl = tid >> 1, o = tid & 1;
        int gr = m0 + rl;
        if (gr < NE) {
            float s = 0.f;
#pragma unroll
            for (int w = 0; w < 8; w++) s += pacc[(w * 128 + rl) * 2 + o];
            out[gr * 2 + o] = s;
        }
    }
}

// ---------------- launch ----------------------------------------------------
extern "C" void kernel_launch(void* const* d_in, const int* in_sizes, int n_in,
                              void* d_out, int out_size) {
    const float* x_email   = (const float*)d_in[0];
    const float* x_url     = (const float*)d_in[1];
    const float* x_sender  = (const float*)d_in[2];
    const float* W_e       = (const float*)d_in[3];
    const float* b_e       = (const float*)d_in[4];
    const float* W_u       = (const float*)d_in[5];
    const float* b_u       = (const float*)d_in[6];
    const float* W_s       = (const float*)d_in[7];
    const float* b_s       = (const float*)d_in[8];
    const float* Wl_ue     = (const float*)d_in[12];
    const float* bl_ue     = (const float*)d_in[13];
    const float* Wr_ue     = (const float*)d_in[14];
    const float* Wl_se     = (const float*)d_in[15];
    const float* bl_se     = (const float*)d_in[16];
    const float* Wr_se     = (const float*)d_in[17];
    const float* gate      = (const float*)d_in[21];
    const float* kan_base  = (const float*)d_in[22];
    const float* kan_spline= (const float*)d_in[23];
    const int*   ue_src    = (const int*)d_in[26];
    const int*   ue_dst    = (const int*)d_in[27];
    const int*   se_src    = (const int*)d_in[28];
    const int*   se_dst    = (const int*)d_in[29];
    int n_ue = in_sizes[26];
    int n_se = in_sizes[28];
    float* out = (float*)d_out;

    cudaFuncSetAttribute((void*)fused_gemm, cudaFuncAttributeMaxDynamicSharedMemorySize,
                         SMEM_BYTES);

    int n_agg_blocks = (n_ue + n_se + 255) / 256;
    zero_kernel<<<512, 256>>>();
    prep_all<<<800 + n_agg_blocks, 256>>>(W_e, Wr_ue, Wr_se, bl_ue, bl_se,
                                          Wl_ue, W_u, b_u, Wl_se, W_s, b_s,
                                          ue_src, ue_dst, x_url, n_ue,
                                          se_src, se_dst, x_sender, n_se);
    fused_gemm<<<(NE + 127) / 128, 1024, SMEM_BYTES>>>(x_email, b_e, gate,
                                                       kan_base, kan_spline, out);
}